// round 15
// baseline (speedup 1.0000x reference)
#include <cuda_runtime.h>
#include <cuda_bf16.h>
#include <math.h>
#include <cstdint>

// ---------------------------------------------------------------------------
// DecoderCell R11: R8/R10 engines; consumer-split gate scheduling.
//  - head: decs chain on s2, enc halves + attention overlapped (R10 style)
//  - x/sprev gates split: gate3 (Vo/Uo) first -> evG3; gates 0-2 -> evG012
//  - ctx gates split: gate3 (Co) on main feeds maxout+logits early;
//    gates 0-2 on s1 feed rz -> Us -> GRU concurrently with logits
// ---------------------------------------------------------------------------

#define B_   64
#define LX_  128
#define HID_ 1024
#define H2_  2048
#define ATN_ 512
#define VOC_ 32000

// -------------------- scratch ---------------------------------------------
__device__ __nv_bfloat16 g_encb[8192 * 2048];
__device__ __nv_bfloat16 g_uab [512 * 2048];
__device__ float g_dpart[8 * 64 * 512];      // decs partials; later Us partials
__device__ float g_decs [64 * 512];
__device__ float g_epart[8192 * 4];
__device__ float g_alpha[8192];
__device__ float g_ctx  [64 * 2048];
__device__ float g_part [7 * 64 * 4096];     // fused-gates split-K partials
__device__ float g_rs   [64 * 1024];         // r * sprev
__device__ float g_z    [64 * 1024];
__device__ float g_t    [64 * 512];          // maxout output (tf32-rounded)

// -------------------- helpers ---------------------------------------------
__device__ __forceinline__ void cpa16(void* smem, const void* g) {
    uint32_t s = (uint32_t)__cvta_generic_to_shared(smem);
    asm volatile("cp.async.cg.shared.global [%0], [%1], 16;\n" :: "r"(s), "l"(g));
}
__device__ __forceinline__ void cpa_commit() { asm volatile("cp.async.commit_group;\n"); }
template <int N> __device__ __forceinline__ void cpa_wait() {
    asm volatile("cp.async.wait_group %0;\n" :: "n"(N));
}

__device__ __forceinline__ float to_tf32(float x) {
    float r;
    asm("cvt.rna.tf32.f32 %0, %1;" : "=f"(r) : "f"(x));
    return r;
}

#define MMA16816(ACC, A0,A1,A2,A3, B0,B1)                                      \
    asm volatile(                                                              \
        "mma.sync.aligned.m16n8k16.row.col.f32.bf16.bf16.f32 "                 \
        "{%0,%1,%2,%3}, {%4,%5,%6,%7}, {%8,%9}, {%0,%1,%2,%3};"                \
        : "+f"((ACC)[0]), "+f"((ACC)[1]), "+f"((ACC)[2]), "+f"((ACC)[3])       \
        : "r"(A0), "r"(A1), "r"(A2), "r"(A3), "r"(B0), "r"(B1))

#define MMA1688T(ACC, A0,A1,A2,A3, B0,B1)                                      \
    asm volatile(                                                              \
        "mma.sync.aligned.m16n8k8.row.col.f32.tf32.tf32.f32 "                  \
        "{%0,%1,%2,%3}, {%4,%5,%6,%7}, {%8,%9}, {%0,%1,%2,%3};"                \
        : "+f"((ACC)[0]), "+f"((ACC)[1]), "+f"((ACC)[2]), "+f"((ACC)[3])       \
        : "r"(A0), "r"(A1), "r"(A2), "r"(A3), "r"(B0), "r"(B1))

#define LDMX4(R, PTR)                                                          \
    do {                                                                       \
        uint32_t _a = (uint32_t)__cvta_generic_to_shared(PTR);                 \
        asm volatile(                                                          \
            "ldmatrix.sync.aligned.m8n8.x4.shared.b16 {%0,%1,%2,%3}, [%4];"    \
            : "=r"((R)[0]), "=r"((R)[1]), "=r"((R)[2]), "=r"((R)[3])           \
            : "r"(_a));                                                        \
    } while (0)

// -------------------- conversions ------------------------------------------
__global__ __launch_bounds__(256) void f2bf_kernel(
    const float* __restrict__ in, __nv_bfloat16* __restrict__ out, int n)
{
    int i = (blockIdx.x * 256 + threadIdx.x) * 4;
    if (i >= n) return;
    float4 v = *(const float4*)(in + i);
    *(__nv_bfloat162*)(out + i)     = __floats2bfloat162_rn(v.x, v.y);
    *(__nv_bfloat162*)(out + i + 2) = __floats2bfloat162_rn(v.z, v.w);
}

// ---------------------------------------------------------------------------
// Attention score GEMM, bf16 HMMA, fused tanh*va epilogue. (R8 version)
// ---------------------------------------------------------------------------
#define AST 72
#define ATILE (128 * AST)

__global__ __launch_bounds__(256) void attn_mma_kernel(
    const __nv_bfloat16* __restrict__ encb, const __nv_bfloat16* __restrict__ uab,
    const float* __restrict__ decs, const float* __restrict__ va,
    float* __restrict__ epart, int m_base)
{
    extern __shared__ char dsm[];
    __nv_bfloat16* As = (__nv_bfloat16*)dsm;
    __nv_bfloat16* Bs = (__nv_bfloat16*)(dsm + 2 * ATILE * 2);
    float* red = (float*)(dsm + 4 * ATILE * 2);

    const int tid = threadIdx.x;
    const int lane = tid & 31;
    const int warp = tid >> 5;
    const int warpM = warp >> 1;
    const int warpN = warp & 1;
    const int g   = lane >> 2;
    const int tig = lane & 3;
    const int m0 = m_base + blockIdx.x * 128;
    const int n0 = blockIdx.y * 128;

    float acc[2][8][4];
    #pragma unroll
    for (int mt = 0; mt < 2; mt++)
        #pragma unroll
        for (int nt = 0; nt < 8; nt++)
            #pragma unroll
            for (int c = 0; c < 4; c++) acc[mt][nt][c] = 0.f;

    auto load_tile = [&](int k0, int st) {
        __nv_bfloat16* A = As + st * ATILE;
        __nv_bfloat16* Bb = Bs + st * ATILE;
        #pragma unroll
        for (int i = 0; i < 4; i++) {
            int idx = tid + 256 * i;
            int r = idx >> 3, c = (idx & 7) * 8;
            cpa16(&A[r * AST + c], encb + (size_t)(m0 + r) * H2_ + k0 + c);
        }
        #pragma unroll
        for (int i = 0; i < 4; i++) {
            int idx = tid + 256 * i;
            int r = idx >> 3, c = (idx & 7) * 8;
            cpa16(&Bb[r * AST + c], uab + (size_t)(n0 + r) * H2_ + k0 + c);
        }
    };

    load_tile(0, 0);
    cpa_commit();

    const int T = H2_ / 64;
    for (int it = 0; it < T; it++) {
        cpa_wait<0>();
        __syncthreads();
        if (it + 1 < T) { load_tile((it + 1) * 64, (it + 1) & 1); cpa_commit(); }

        const __nv_bfloat16* A = As + (it & 1) * ATILE;
        const __nv_bfloat16* Bb = Bs + (it & 1) * ATILE;

        #pragma unroll
        for (int kf = 0; kf < 4; kf++) {
            uint32_t a[2][4];
            #pragma unroll
            for (int mt = 0; mt < 2; mt++)
                LDMX4(a[mt], &A[(warpM * 32 + mt * 16 + (lane & 15)) * AST
                                + kf * 16 + (lane >> 4) * 8]);
            #pragma unroll
            for (int j = 0; j < 4; j++) {
                uint32_t bfr[4];
                const int bn = warpN * 64 + j * 16 + (lane & 7) + ((lane >> 4) << 3);
                const int bc = kf * 16 + ((lane >> 3) & 1) * 8;
                LDMX4(bfr, &Bb[bn * AST + bc]);
                #pragma unroll
                for (int h = 0; h < 2; h++) {
                    const int nt = 2 * j + h;
                    #pragma unroll
                    for (int mt = 0; mt < 2; mt++)
                        MMA16816(acc[mt][nt], a[mt][0], a[mt][1], a[mt][2], a[mt][3],
                                 bfr[h * 2], bfr[h * 2 + 1]);
                }
            }
        }
        __syncthreads();
    }

    float rowsum[2][2] = {{0.f, 0.f}, {0.f, 0.f}};
    #pragma unroll
    for (int mt = 0; mt < 2; mt++) {
        const int rbase = warpM * 32 + mt * 16 + g;
        const int b1 = rbase & 63;
        const int b2 = (rbase + 8) & 63;
        #pragma unroll
        for (int nt = 0; nt < 8; nt++) {
            const int a0 = n0 + warpN * 64 + nt * 8 + tig * 2;
            const float va0 = va[a0], va1 = va[a0 + 1];
            const float d10 = decs[b1 * ATN_ + a0], d11 = decs[b1 * ATN_ + a0 + 1];
            const float d20 = decs[b2 * ATN_ + a0], d21 = decs[b2 * ATN_ + a0 + 1];
            rowsum[mt][0] += tanhf(acc[mt][nt][0] + d10) * va0
                           + tanhf(acc[mt][nt][1] + d11) * va1;
            rowsum[mt][1] += tanhf(acc[mt][nt][2] + d20) * va0
                           + tanhf(acc[mt][nt][3] + d21) * va1;
        }
    }
    #pragma unroll
    for (int mt = 0; mt < 2; mt++)
        #pragma unroll
        for (int h = 0; h < 2; h++) {
            rowsum[mt][h] += __shfl_xor_sync(0xffffffffu, rowsum[mt][h], 1);
            rowsum[mt][h] += __shfl_xor_sync(0xffffffffu, rowsum[mt][h], 2);
        }
    if (tig == 0) {
        #pragma unroll
        for (int mt = 0; mt < 2; mt++)
            #pragma unroll
            for (int h = 0; h < 2; h++)
                red[(warpM * 32 + mt * 16 + g + h * 8) * 2 + warpN] = rowsum[mt][h];
    }
    __syncthreads();
    if (tid < 128)
        epart[(size_t)(m0 + tid) * 4 + blockIdx.y] = red[tid * 2] + red[tid * 2 + 1];
}

// ---------------------------------------------------------------------------
// cp.async 4-stage TF32 GEMM engine (unchanged).
// ---------------------------------------------------------------------------
#define KST 36

struct GemmP {
    const float* A[7];
    int          lda[7];
    const float* W[4][7];
    int          ldw[7];
    float*       C[7];
    int          ldc;
    int          gshift;
    int          gate_cols;
    int          kiters;
    int          cvtA;
    int          cvtB;
};

__global__ __launch_bounds__(256, 3) void gemm_async_kernel(GemmP p)
{
    extern __shared__ float sm[];
    float* As = sm;
    float* Bs = sm + 4 * 64 * KST;

    const int chunk = blockIdx.y;
    const int gate  = blockIdx.x >> p.gshift;
    const float* Wp = p.W[gate][chunk];
    if (Wp == nullptr) return;
    const int n0g = blockIdx.x * 64 - gate * p.gate_cols;
    const float* Ap = p.A[chunk];
    const int lda = p.lda[chunk];
    const int ldw = p.ldw[chunk];
    float* Cp = p.C[chunk];

    const int tid = threadIdx.x;
    const int lane = tid & 31;
    const int warp = tid >> 5;
    const int warpM = warp >> 2;
    const int warpN = warp & 3;
    const int g   = lane >> 2;
    const int tig = lane & 3;

    auto load_stage = [&](int it) {
        const int k0 = it * 32;
        float* Ad = As + (it & 3) * 64 * KST;
        float* Bd = Bs + (it & 3) * 64 * KST;
        #pragma unroll
        for (int i = 0; i < 2; i++) {
            int idx = tid + 256 * i;
            int r = idx >> 3, c = (idx & 7) * 4;
            cpa16(&Ad[r * KST + c], Ap + (size_t)r * lda + k0 + c);
            cpa16(&Bd[r * KST + c], Wp + (size_t)(n0g + r) * ldw + k0 + c);
        }
        cpa_commit();
    };

    float acc[2][2][4];
    #pragma unroll
    for (int mt = 0; mt < 2; mt++)
        #pragma unroll
        for (int nf = 0; nf < 2; nf++)
            #pragma unroll
            for (int c = 0; c < 4; c++) acc[mt][nf][c] = 0.f;

    const int T = p.kiters;
    load_stage(0); load_stage(1); load_stage(2);

    for (int it = 0; it < T; it++) {
        if (it <= T - 3)      cpa_wait<2>();
        else if (it == T - 2) cpa_wait<1>();
        else                  cpa_wait<0>();
        __syncthreads();
        if (it + 3 < T) load_stage(it + 3);

        const float* Asm = As + (it & 3) * 64 * KST;
        const float* Bsm = Bs + (it & 3) * 64 * KST;

        #pragma unroll
        for (int kf = 0; kf < 4; kf++) {
            float af[2][4];
            #pragma unroll
            for (int mt = 0; mt < 2; mt++) {
                const int row = warpM * 32 + mt * 16 + g;
                af[mt][0] = Asm[row * KST + kf * 8 + tig];
                af[mt][1] = Asm[(row + 8) * KST + kf * 8 + tig];
                af[mt][2] = Asm[row * KST + kf * 8 + tig + 4];
                af[mt][3] = Asm[(row + 8) * KST + kf * 8 + tig + 4];
                if (p.cvtA) {
                    af[mt][0] = to_tf32(af[mt][0]); af[mt][1] = to_tf32(af[mt][1]);
                    af[mt][2] = to_tf32(af[mt][2]); af[mt][3] = to_tf32(af[mt][3]);
                }
            }
            #pragma unroll
            for (int nf = 0; nf < 2; nf++) {
                const int brow = warpN * 16 + nf * 8 + g;
                float b0f = Bsm[brow * KST + kf * 8 + tig];
                float b1f = Bsm[brow * KST + kf * 8 + tig + 4];
                if (p.cvtB) { b0f = to_tf32(b0f); b1f = to_tf32(b1f); }
                const uint32_t b0 = __float_as_uint(b0f);
                const uint32_t b1 = __float_as_uint(b1f);
                #pragma unroll
                for (int mt = 0; mt < 2; mt++)
                    MMA1688T(acc[mt][nf],
                             __float_as_uint(af[mt][0]), __float_as_uint(af[mt][1]),
                             __float_as_uint(af[mt][2]), __float_as_uint(af[mt][3]),
                             b0, b1);
            }
        }
        __syncthreads();
    }

    #pragma unroll
    for (int mt = 0; mt < 2; mt++) {
        const int r1 = warpM * 32 + mt * 16 + g;
        const int r2 = r1 + 8;
        #pragma unroll
        for (int nf = 0; nf < 2; nf++) {
            const int ncol = blockIdx.x * 64 + warpN * 16 + nf * 8 + tig * 2;
            *(float2*)(Cp + (size_t)r1 * p.ldc + ncol) =
                make_float2(acc[mt][nf][0], acc[mt][nf][1]);
            *(float2*)(Cp + (size_t)r2 * p.ldc + ncol) =
                make_float2(acc[mt][nf][2], acc[mt][nf][3]);
        }
    }
}

// ---------------------------------------------------------------------------
// fp32 NT GEMM partial (split-K) — decs only.
// ---------------------------------------------------------------------------
__global__ __launch_bounds__(256) void gemm_part_kernel(
    const float* __restrict__ A, int lda,
    const float* __restrict__ W, int ldw,
    float* __restrict__ Cpart, int N, int kchunk)
{
    __shared__ float As[16][64];
    __shared__ float Bs[16][64];
    const int tid = threadIdx.x;
    const int tx = tid & 15, ty = tid >> 4;
    const int n0 = blockIdx.x * 64;
    const int kbase = blockIdx.y * kchunk;
    const int lm = tid >> 2;
    const int lk = (tid & 3) * 4;

    float acc[4][4] = {};
    for (int k0 = 0; k0 < kchunk; k0 += 16) {
        float4 av = *(const float4*)(A + (size_t)lm * lda + kbase + k0 + lk);
        As[lk + 0][lm] = av.x; As[lk + 1][lm] = av.y;
        As[lk + 2][lm] = av.z; As[lk + 3][lm] = av.w;
        float4 bv = *(const float4*)(W + (size_t)(n0 + lm) * ldw + kbase + k0 + lk);
        Bs[lk + 0][lm] = bv.x; Bs[lk + 1][lm] = bv.y;
        Bs[lk + 2][lm] = bv.z; Bs[lk + 3][lm] = bv.w;
        __syncthreads();
        #pragma unroll
        for (int k = 0; k < 16; k++) {
            float4 a = *(const float4*)&As[k][ty * 4];
            float4 b = *(const float4*)&Bs[k][tx * 4];
            acc[0][0] += a.x * b.x; acc[0][1] += a.x * b.y; acc[0][2] += a.x * b.z; acc[0][3] += a.x * b.w;
            acc[1][0] += a.y * b.x; acc[1][1] += a.y * b.y; acc[1][2] += a.y * b.z; acc[1][3] += a.y * b.w;
            acc[2][0] += a.z * b.x; acc[2][1] += a.z * b.y; acc[2][2] += a.z * b.z; acc[2][3] += a.z * b.w;
            acc[3][0] += a.w * b.x; acc[3][1] += a.w * b.y; acc[3][2] += a.w * b.z; acc[3][3] += a.w * b.w;
        }
        __syncthreads();
    }
    float* Cout = Cpart + (size_t)blockIdx.y * 64 * N;
    #pragma unroll
    for (int i = 0; i < 4; i++)
        *(float4*)(Cout + (size_t)(ty * 4 + i) * N + n0 + tx * 4) =
            make_float4(acc[i][0], acc[i][1], acc[i][2], acc[i][3]);
}

// softmax over l per batch column b. grid=64, block=128
__global__ void softmax_kernel(const float* __restrict__ epart, float* __restrict__ alpha)
{
    const int b = blockIdx.x;
    const int l = threadIdx.x;
    __shared__ float sm[128];
    const float* p = epart + (size_t)(l * B_ + b) * 4;
    float ev = p[0] + p[1] + p[2] + p[3];
    sm[l] = ev; __syncthreads();
    for (int o = 64; o > 0; o >>= 1) { if (l < o) sm[l] = fmaxf(sm[l], sm[l + o]); __syncthreads(); }
    const float mx = sm[0]; __syncthreads();
    const float ex = expf(ev - mx);
    sm[l] = ex; __syncthreads();
    for (int o = 64; o > 0; o >>= 1) { if (l < o) sm[l] += sm[l + o]; __syncthreads(); }
    alpha[l * B_ + b] = ex / sm[0];
}

// context: c[b,h] = sum_l alpha[l,b] * enc[l,b,h].  grid=(64,8), block=256
__global__ void ctx_kernel(const float* __restrict__ alpha,
                           const float* __restrict__ enc, float* __restrict__ ctx)
{
    const int b = blockIdx.x;
    const int h = blockIdx.y * 256 + threadIdx.x;
    __shared__ float al[128];
    if (threadIdx.x < 128) al[threadIdx.x] = alpha[threadIdx.x * B_ + b];
    __syncthreads();
    float acc = 0.f;
    #pragma unroll 4
    for (int l = 0; l < LX_; l++)
        acc += al[l] * enc[(size_t)(l * B_ + b) * H2_ + h];
    ctx[b * H2_ + h] = acc;
}

// -------------------- combiners -------------------------------------------
__global__ void combine_plain(const float* __restrict__ part, int nchunks,
                              int nelem, float* __restrict__ out)
{
    const int i = blockIdx.x * 256 + threadIdx.x;
    if (i >= nelem) return;
    float s = 0.f;
    for (int c = 0; c < nchunks; c++) s += part[(size_t)c * nelem + i];
    out[i] = s;
}

__global__ void combine_rz(const float* __restrict__ part,
                           const float* __restrict__ br, const float* __restrict__ bz,
                           const float* __restrict__ sprev,
                           float* __restrict__ rs, float* __restrict__ z)
{
    const int i = blockIdx.x * 256 + threadIdx.x;
    const int m = i >> 11, n = i & 2047;
    float s = (n < 1024) ? br[n] : bz[n - 1024];
    #pragma unroll
    for (int c = 0; c < 7; c++) s += part[(size_t)c * 64 * 4096 + m * 4096 + n];
    const float v = 1.f / (1.f + expf(-s));
    if (n < 1024) rs[m * 1024 + n] = v * sprev[m * 1024 + n];
    else          z[m * 1024 + n - 1024] = v;
}

__global__ void combine_gru(const float* __restrict__ part, const float* __restrict__ uspart,
                            const float* __restrict__ bs, const float* __restrict__ z,
                            const float* __restrict__ sprev, float* __restrict__ s_out)
{
    const int i = blockIdx.x * 256 + threadIdx.x;
    const int m = i >> 10, n = i & 1023;
    float acc = bs[n];
    const int col = 2048 + n;
    acc += part[(size_t)0 * 64 * 4096 + m * 4096 + col];
    #pragma unroll
    for (int c = 3; c < 7; c++) acc += part[(size_t)c * 64 * 4096 + m * 4096 + col];
    #pragma unroll
    for (int c = 0; c < 4; c++) acc += uspart[c * 65536 + m * 1024 + n];
    const float sp = tanhf(acc);
    const float zz = z[i];
    s_out[i] = zz * sp + (1.f - zz) * sprev[i];
}

__global__ void combine_maxout(const float* __restrict__ part, float* __restrict__ t)
{
    const int i = blockIdx.x * 256 + threadIdx.x;
    const int m = i >> 9, j = i & 511;
    const int c0 = 3072 + 2 * j;
    float v0 = 0.f, v1 = 0.f;
    #pragma unroll
    for (int c = 0; c < 7; c++) {
        const float* p = part + (size_t)c * 64 * 4096 + m * 4096;
        v0 += p[c0]; v1 += p[c0 + 1];
    }
    float r;
    asm("cvt.rna.tf32.f32 %0, %1;" : "=f"(r) : "f"(fmaxf(v0, v1)));
    t[i] = r;
}

// ---------------------------------------------------------------------------
extern "C" void kernel_launch(void* const* d_in, const int* in_sizes, int n_in,
                              void* d_out, int out_size)
{
    const float* x     = (const float*)d_in[0];
    const float* sprev = (const float*)d_in[1];
    const float* enc   = (const float*)d_in[2];
    const float* Ws = (const float*)d_in[4];
    const float* Wz = (const float*)d_in[5];
    const float* Wr = (const float*)d_in[6];
    const float* Us = (const float*)d_in[7];
    const float* Uz = (const float*)d_in[8];
    const float* Ur = (const float*)d_in[9];
    const float* Cs = (const float*)d_in[10];
    const float* Cz = (const float*)d_in[11];
    const float* Cr = (const float*)d_in[12];
    const float* bs = (const float*)d_in[13];
    const float* bz = (const float*)d_in[14];
    const float* br = (const float*)d_in[15];
    const float* va = (const float*)d_in[16];
    const float* Wa = (const float*)d_in[17];
    const float* Ua = (const float*)d_in[18];
    const float* Uo = (const float*)d_in[19];
    const float* Vo = (const float*)d_in[20];
    const float* Co = (const float*)d_in[21];
    const float* Wo = (const float*)d_in[22];

    static float *p_dpart = nullptr, *p_decs, *p_epart, *p_alpha, *p_ctx,
                 *p_part, *p_rs, *p_z, *p_t;
    static __nv_bfloat16 *p_encb, *p_uab;
    static cudaStream_t s1, s2;
    static cudaEvent_t ev_root, evA, evB2, evG3, evG012, evCtx, evC;
    static int attn_smem = 4 * ATILE * 2 + 128 * 2 * 4;
    static int eng_smem  = 8 * 64 * KST * 4;
    if (!p_dpart) {
        cudaGetSymbolAddress((void**)&p_dpart, g_dpart);
        cudaGetSymbolAddress((void**)&p_decs,  g_decs);
        cudaGetSymbolAddress((void**)&p_epart, g_epart);
        cudaGetSymbolAddress((void**)&p_alpha, g_alpha);
        cudaGetSymbolAddress((void**)&p_ctx,   g_ctx);
        cudaGetSymbolAddress((void**)&p_part,  g_part);
        cudaGetSymbolAddress((void**)&p_rs,    g_rs);
        cudaGetSymbolAddress((void**)&p_z,     g_z);
        cudaGetSymbolAddress((void**)&p_t,     g_t);
        cudaGetSymbolAddress((void**)&p_encb,  g_encb);
        cudaGetSymbolAddress((void**)&p_uab,   g_uab);
        cudaFuncSetAttribute(attn_mma_kernel,
                             cudaFuncAttributeMaxDynamicSharedMemorySize, attn_smem);
        cudaFuncSetAttribute(gemm_async_kernel,
                             cudaFuncAttributeMaxDynamicSharedMemorySize, eng_smem);
        cudaStreamCreateWithFlags(&s1, cudaStreamNonBlocking);
        cudaStreamCreateWithFlags(&s2, cudaStreamNonBlocking);
        cudaEventCreateWithFlags(&ev_root, cudaEventDisableTiming);
        cudaEventCreateWithFlags(&evA, cudaEventDisableTiming);
        cudaEventCreateWithFlags(&evB2, cudaEventDisableTiming);
        cudaEventCreateWithFlags(&evG3, cudaEventDisableTiming);
        cudaEventCreateWithFlags(&evG012, cudaEventDisableTiming);
        cudaEventCreateWithFlags(&evCtx, cudaEventDisableTiming);
        cudaEventCreateWithFlags(&evC, cudaEventDisableTiming);
    }

    float* out_s      = (float*)d_out;
    float* out_logits = (float*)d_out + 65536;

    const int HALF = 4096 * 2048;   // half of enc, in elements

    // ---- fork head --------------------------------------------------------
    cudaEventRecord(ev_root, 0);
    cudaStreamWaitEvent(s1, ev_root, 0);
    cudaStreamWaitEvent(s2, ev_root, 0);

    // s2: decs chain, then x/sprev gate3 (for logits path), then gates 0-2
    f2bf_kernel<<<1024, 256, 0, s2>>>(Ua, p_uab, 512 * 2048);
    gemm_part_kernel<<<dim3(8, 8), 256, 0, s2>>>(sprev, HID_, Wa, HID_, p_dpart, ATN_, 128);
    combine_plain<<<128, 256, 0, s2>>>(p_dpart, 8, 64 * ATN_, p_decs);
    cudaEventRecord(evA, s2);
    {
        // x/sprev gate 3 only (t_tilde from Vo/Uo), cols 3072..4095
        GemmP p = {};
        const float* Aseq[3] = { x, sprev, sprev + 512 };
        int ldas[3] = { 512, 1024, 1024 };
        const float* Wt3[3] = { Vo, Uo, Uo + 512 };
        for (int c = 0; c < 3; c++) {
            p.A[c] = Aseq[c]; p.lda[c] = ldas[c]; p.ldw[c] = ldas[c];
            p.W[0][c] = Wt3[c];
            p.C[c] = p_part + (size_t)c * 64 * 4096 + 3072;
        }
        p.ldc = 4096; p.gshift = 16; p.gate_cols = 0;
        p.kiters = 16; p.cvtA = 1; p.cvtB = 1;
        gemm_async_kernel<<<dim3(16, 3), 256, eng_smem, s2>>>(p);
    }
    cudaEventRecord(evG3, s2);
    {
        // x/sprev gates 0-2 (r, z, s)
        GemmP p = {};
        const float* Aseq[3] = { x, sprev, sprev + 512 };
        int ldas[3] = { 512, 1024, 1024 };
        for (int c = 0; c < 3; c++) {
            p.A[c] = Aseq[c]; p.lda[c] = ldas[c]; p.ldw[c] = ldas[c];
            p.C[c] = p_part + (size_t)c * 64 * 4096;
        }
        const float* Wt[3][3] = {
            { Wr, Ur, Ur + 512 },
            { Wz, Uz, Uz + 512 },
            { Ws, nullptr, nullptr },
        };
        for (int gg = 0; gg < 3; gg++)
            for (int c = 0; c < 3; c++) p.W[gg][c] = Wt[gg][c];
        p.ldc = 4096; p.gshift = 4; p.gate_cols = 1024;
        p.kiters = 16; p.cvtA = 1; p.cvtB = 1;
        gemm_async_kernel<<<dim3(48, 3), 256, eng_smem, s2>>>(p);
    }
    cudaEventRecord(evG012, s2);

    // s1: enc upper-half conversion, attention upper half (after decs)
    f2bf_kernel<<<8192, 256, 0, s1>>>(enc + HALF, p_encb + HALF, HALF);
    cudaStreamWaitEvent(s1, evA, 0);
    attn_mma_kernel<<<dim3(32, 4), 256, attn_smem, s1>>>(
        p_encb, p_uab, p_decs, va, p_epart, 4096);
    cudaEventRecord(evB2, s1);

    // main: enc lower-half conversion, attention lower half
    f2bf_kernel<<<8192, 256>>>(enc, p_encb, HALF);
    cudaStreamWaitEvent(0, evA, 0);
    attn_mma_kernel<<<dim3(32, 4), 256, attn_smem>>>(
        p_encb, p_uab, p_decs, va, p_epart, 0);

    // join halves; softmax; ctx
    cudaStreamWaitEvent(0, evB2, 0);
    softmax_kernel<<<64, 128>>>(p_epart, p_alpha);
    ctx_kernel<<<dim3(64, 8), 256>>>(p_alpha, enc, p_ctx);
    cudaEventRecord(evCtx, 0);

    // main (logits path): ctx gate3 (Co) -> maxout -> logits
    {
        GemmP p = {};
        const float* Wt3[4] = { Co, Co + 512, Co + 1024, Co + 1536 };
        for (int c = 0; c < 4; c++) {
            p.A[c] = p_ctx + c * 512;
            p.lda[c] = 2048; p.ldw[c] = 2048;
            p.W[0][c] = Wt3[c];
            p.C[c] = p_part + (size_t)(c + 3) * 64 * 4096 + 3072;
        }
        p.ldc = 4096; p.gshift = 16; p.gate_cols = 0;
        p.kiters = 16; p.cvtA = 1; p.cvtB = 1;
        gemm_async_kernel<<<dim3(16, 4), 256, eng_smem>>>(p);
    }
    cudaStreamWaitEvent(0, evG3, 0);
    combine_maxout<<<128, 256>>>(p_part, p_t);
    {
        GemmP p = {};
        p.A[0] = p_t; p.lda[0] = 512;
        p.W[0][0] = Wo; p.ldw[0] = 512;
        p.C[0] = out_logits; p.ldc = VOC_;
        p.gshift = 16; p.gate_cols = 0;
        p.kiters = 16; p.cvtA = 0; p.cvtB = 1;
        gemm_async_kernel<<<dim3(500, 1), 256, eng_smem>>>(p);
    }

    // s1 (s-output path): ctx gates 0-2 -> rz -> Us -> GRU blend
    cudaStreamWaitEvent(s1, evCtx, 0);
    {
        GemmP p = {};
        for (int c = 0; c < 4; c++) {
            p.A[c] = p_ctx + c * 512;
            p.lda[c] = 2048; p.ldw[c] = 2048;
            p.C[c] = p_part + (size_t)(c + 3) * 64 * 4096;
        }
        const float* Wt[3][4] = {
            { Cr, Cr + 512, Cr + 1024, Cr + 1536 },
            { Cz, Cz + 512, Cz + 1024, Cz + 1536 },
            { Cs, Cs + 512, Cs + 1024, Cs + 1536 },
        };
        for (int gg = 0; gg < 3; gg++)
            for (int c = 0; c < 4; c++) p.W[gg][c] = Wt[gg][c];
        p.ldc = 4096; p.gshift = 4; p.gate_cols = 1024;
        p.kiters = 16; p.cvtA = 1; p.cvtB = 1;
        gemm_async_kernel<<<dim3(48, 4), 256, eng_smem, s1>>>(p);
    }
    cudaStreamWaitEvent(s1, evG012, 0);
    combine_rz<<<512, 256, 0, s1>>>(p_part, br, bz, sprev, p_rs, p_z);
    {
        GemmP p = {};
        for (int c = 0; c < 4; c++) {
            p.A[c] = p_rs + c * 256;
            p.lda[c] = 1024; p.ldw[c] = 1024;
            p.W[0][c] = Us + c * 256;
            p.C[c] = p_dpart + (size_t)c * 65536;
        }
        p.ldc = 1024; p.gshift = 16; p.gate_cols = 0;
        p.kiters = 8; p.cvtA = 1; p.cvtB = 1;
        gemm_async_kernel<<<dim3(16, 4), 256, eng_smem, s1>>>(p);
    }
    combine_gru<<<256, 256, 0, s1>>>(p_part, p_dpart, bs, p_z, sprev, out_s);
    cudaEventRecord(evC, s1);

    cudaStreamWaitEvent(0, evC, 0);
}

// round 17
// speedup vs baseline: 1.6818x; 1.6818x over previous
#include <cuda_runtime.h>
#include <cuda_bf16.h>
#include <math.h>
#include <cstdint>

// ---------------------------------------------------------------------------
// DecoderCell R12 = R8 (best known: 194.7us) + softmax fused into ctx kernel.
//  - attention: bf16 HMMA halves overlapped with enc conversion halves
//  - gates/Us/logits: cp.async 4-stage TF32 engine, FUSED launches (the
//    engine has a ~20-30us latency floor per launch; never split it)
//  - x/sprev gates on s2; tail fork: s-chain on s1 vs maxout+logits on main
// ---------------------------------------------------------------------------

#define B_   64
#define LX_  128
#define HID_ 1024
#define H2_  2048
#define ATN_ 512
#define VOC_ 32000

// -------------------- scratch ---------------------------------------------
__device__ __nv_bfloat16 g_encb[8192 * 2048];
__device__ __nv_bfloat16 g_uab [512 * 2048];
__device__ float g_dpart[8 * 64 * 512];      // decs partials; later Us partials
__device__ float g_decs [64 * 512];
__device__ float g_epart[8192 * 4];
__device__ float g_ctx  [64 * 2048];
__device__ float g_part [7 * 64 * 4096];     // fused-gates split-K partials
__device__ float g_rs   [64 * 1024];         // r * sprev
__device__ float g_z    [64 * 1024];
__device__ float g_t    [64 * 512];          // maxout output (tf32-rounded)

// -------------------- helpers ---------------------------------------------
__device__ __forceinline__ void cpa16(void* smem, const void* g) {
    uint32_t s = (uint32_t)__cvta_generic_to_shared(smem);
    asm volatile("cp.async.cg.shared.global [%0], [%1], 16;\n" :: "r"(s), "l"(g));
}
__device__ __forceinline__ void cpa_commit() { asm volatile("cp.async.commit_group;\n"); }
template <int N> __device__ __forceinline__ void cpa_wait() {
    asm volatile("cp.async.wait_group %0;\n" :: "n"(N));
}

__device__ __forceinline__ float to_tf32(float x) {
    float r;
    asm("cvt.rna.tf32.f32 %0, %1;" : "=f"(r) : "f"(x));
    return r;
}

#define MMA16816(ACC, A0,A1,A2,A3, B0,B1)                                      \
    asm volatile(                                                              \
        "mma.sync.aligned.m16n8k16.row.col.f32.bf16.bf16.f32 "                 \
        "{%0,%1,%2,%3}, {%4,%5,%6,%7}, {%8,%9}, {%0,%1,%2,%3};"                \
        : "+f"((ACC)[0]), "+f"((ACC)[1]), "+f"((ACC)[2]), "+f"((ACC)[3])       \
        : "r"(A0), "r"(A1), "r"(A2), "r"(A3), "r"(B0), "r"(B1))

#define MMA1688T(ACC, A0,A1,A2,A3, B0,B1)                                      \
    asm volatile(                                                              \
        "mma.sync.aligned.m16n8k8.row.col.f32.tf32.tf32.f32 "                  \
        "{%0,%1,%2,%3}, {%4,%5,%6,%7}, {%8,%9}, {%0,%1,%2,%3};"                \
        : "+f"((ACC)[0]), "+f"((ACC)[1]), "+f"((ACC)[2]), "+f"((ACC)[3])       \
        : "r"(A0), "r"(A1), "r"(A2), "r"(A3), "r"(B0), "r"(B1))

#define LDMX4(R, PTR)                                                          \
    do {                                                                       \
        uint32_t _a = (uint32_t)__cvta_generic_to_shared(PTR);                 \
        asm volatile(                                                          \
            "ldmatrix.sync.aligned.m8n8.x4.shared.b16 {%0,%1,%2,%3}, [%4];"    \
            : "=r"((R)[0]), "=r"((R)[1]), "=r"((R)[2]), "=r"((R)[3])           \
            : "r"(_a));                                                        \
    } while (0)

// -------------------- conversions ------------------------------------------
__global__ __launch_bounds__(256) void f2bf_kernel(
    const float* __restrict__ in, __nv_bfloat16* __restrict__ out, int n)
{
    int i = (blockIdx.x * 256 + threadIdx.x) * 4;
    if (i >= n) return;
    float4 v = *(const float4*)(in + i);
    *(__nv_bfloat162*)(out + i)     = __floats2bfloat162_rn(v.x, v.y);
    *(__nv_bfloat162*)(out + i + 2) = __floats2bfloat162_rn(v.z, v.w);
}

// ---------------------------------------------------------------------------
// Attention score GEMM, bf16 HMMA, fused tanh*va epilogue. (R8 version)
// ---------------------------------------------------------------------------
#define AST 72
#define ATILE (128 * AST)

__global__ __launch_bounds__(256) void attn_mma_kernel(
    const __nv_bfloat16* __restrict__ encb, const __nv_bfloat16* __restrict__ uab,
    const float* __restrict__ decs, const float* __restrict__ va,
    float* __restrict__ epart, int m_base)
{
    extern __shared__ char dsm[];
    __nv_bfloat16* As = (__nv_bfloat16*)dsm;
    __nv_bfloat16* Bs = (__nv_bfloat16*)(dsm + 2 * ATILE * 2);
    float* red = (float*)(dsm + 4 * ATILE * 2);

    const int tid = threadIdx.x;
    const int lane = tid & 31;
    const int warp = tid >> 5;
    const int warpM = warp >> 1;
    const int warpN = warp & 1;
    const int g   = lane >> 2;
    const int tig = lane & 3;
    const int m0 = m_base + blockIdx.x * 128;
    const int n0 = blockIdx.y * 128;

    float acc[2][8][4];
    #pragma unroll
    for (int mt = 0; mt < 2; mt++)
        #pragma unroll
        for (int nt = 0; nt < 8; nt++)
            #pragma unroll
            for (int c = 0; c < 4; c++) acc[mt][nt][c] = 0.f;

    auto load_tile = [&](int k0, int st) {
        __nv_bfloat16* A = As + st * ATILE;
        __nv_bfloat16* Bb = Bs + st * ATILE;
        #pragma unroll
        for (int i = 0; i < 4; i++) {
            int idx = tid + 256 * i;
            int r = idx >> 3, c = (idx & 7) * 8;
            cpa16(&A[r * AST + c], encb + (size_t)(m0 + r) * H2_ + k0 + c);
        }
        #pragma unroll
        for (int i = 0; i < 4; i++) {
            int idx = tid + 256 * i;
            int r = idx >> 3, c = (idx & 7) * 8;
            cpa16(&Bb[r * AST + c], uab + (size_t)(n0 + r) * H2_ + k0 + c);
        }
    };

    load_tile(0, 0);
    cpa_commit();

    const int T = H2_ / 64;
    for (int it = 0; it < T; it++) {
        cpa_wait<0>();
        __syncthreads();
        if (it + 1 < T) { load_tile((it + 1) * 64, (it + 1) & 1); cpa_commit(); }

        const __nv_bfloat16* A = As + (it & 1) * ATILE;
        const __nv_bfloat16* Bb = Bs + (it & 1) * ATILE;

        #pragma unroll
        for (int kf = 0; kf < 4; kf++) {
            uint32_t a[2][4];
            #pragma unroll
            for (int mt = 0; mt < 2; mt++)
                LDMX4(a[mt], &A[(warpM * 32 + mt * 16 + (lane & 15)) * AST
                                + kf * 16 + (lane >> 4) * 8]);
            #pragma unroll
            for (int j = 0; j < 4; j++) {
                uint32_t bfr[4];
                const int bn = warpN * 64 + j * 16 + (lane & 7) + ((lane >> 4) << 3);
                const int bc = kf * 16 + ((lane >> 3) & 1) * 8;
                LDMX4(bfr, &Bb[bn * AST + bc]);
                #pragma unroll
                for (int h = 0; h < 2; h++) {
                    const int nt = 2 * j + h;
                    #pragma unroll
                    for (int mt = 0; mt < 2; mt++)
                        MMA16816(acc[mt][nt], a[mt][0], a[mt][1], a[mt][2], a[mt][3],
                                 bfr[h * 2], bfr[h * 2 + 1]);
                }
            }
        }
        __syncthreads();
    }

    float rowsum[2][2] = {{0.f, 0.f}, {0.f, 0.f}};
    #pragma unroll
    for (int mt = 0; mt < 2; mt++) {
        const int rbase = warpM * 32 + mt * 16 + g;
        const int b1 = rbase & 63;
        const int b2 = (rbase + 8) & 63;
        #pragma unroll
        for (int nt = 0; nt < 8; nt++) {
            const int a0 = n0 + warpN * 64 + nt * 8 + tig * 2;
            const float va0 = va[a0], va1 = va[a0 + 1];
            const float d10 = decs[b1 * ATN_ + a0], d11 = decs[b1 * ATN_ + a0 + 1];
            const float d20 = decs[b2 * ATN_ + a0], d21 = decs[b2 * ATN_ + a0 + 1];
            rowsum[mt][0] += tanhf(acc[mt][nt][0] + d10) * va0
                           + tanhf(acc[mt][nt][1] + d11) * va1;
            rowsum[mt][1] += tanhf(acc[mt][nt][2] + d20) * va0
                           + tanhf(acc[mt][nt][3] + d21) * va1;
        }
    }
    #pragma unroll
    for (int mt = 0; mt < 2; mt++)
        #pragma unroll
        for (int h = 0; h < 2; h++) {
            rowsum[mt][h] += __shfl_xor_sync(0xffffffffu, rowsum[mt][h], 1);
            rowsum[mt][h] += __shfl_xor_sync(0xffffffffu, rowsum[mt][h], 2);
        }
    if (tig == 0) {
        #pragma unroll
        for (int mt = 0; mt < 2; mt++)
            #pragma unroll
            for (int h = 0; h < 2; h++)
                red[(warpM * 32 + mt * 16 + g + h * 8) * 2 + warpN] = rowsum[mt][h];
    }
    __syncthreads();
    if (tid < 128)
        epart[(size_t)(m0 + tid) * 4 + blockIdx.y] = red[tid * 2] + red[tid * 2 + 1];
}

// ---------------------------------------------------------------------------
// cp.async 4-stage TF32 GEMM engine (unchanged).
// ---------------------------------------------------------------------------
#define KST 36

struct GemmP {
    const float* A[7];
    int          lda[7];
    const float* W[4][7];
    int          ldw[7];
    float*       C[7];
    int          ldc;
    int          gshift;
    int          gate_cols;
    int          kiters;
    int          cvtA;
    int          cvtB;
};

__global__ __launch_bounds__(256, 3) void gemm_async_kernel(GemmP p)
{
    extern __shared__ float sm[];
    float* As = sm;
    float* Bs = sm + 4 * 64 * KST;

    const int chunk = blockIdx.y;
    const int gate  = blockIdx.x >> p.gshift;
    const float* Wp = p.W[gate][chunk];
    if (Wp == nullptr) return;
    const int n0g = blockIdx.x * 64 - gate * p.gate_cols;
    const float* Ap = p.A[chunk];
    const int lda = p.lda[chunk];
    const int ldw = p.ldw[chunk];
    float* Cp = p.C[chunk];

    const int tid = threadIdx.x;
    const int lane = tid & 31;
    const int warp = tid >> 5;
    const int warpM = warp >> 2;
    const int warpN = warp & 3;
    const int g   = lane >> 2;
    const int tig = lane & 3;

    auto load_stage = [&](int it) {
        const int k0 = it * 32;
        float* Ad = As + (it & 3) * 64 * KST;
        float* Bd = Bs + (it & 3) * 64 * KST;
        #pragma unroll
        for (int i = 0; i < 2; i++) {
            int idx = tid + 256 * i;
            int r = idx >> 3, c = (idx & 7) * 4;
            cpa16(&Ad[r * KST + c], Ap + (size_t)r * lda + k0 + c);
            cpa16(&Bd[r * KST + c], Wp + (size_t)(n0g + r) * ldw + k0 + c);
        }
        cpa_commit();
    };

    float acc[2][2][4];
    #pragma unroll
    for (int mt = 0; mt < 2; mt++)
        #pragma unroll
        for (int nf = 0; nf < 2; nf++)
            #pragma unroll
            for (int c = 0; c < 4; c++) acc[mt][nf][c] = 0.f;

    const int T = p.kiters;
    load_stage(0); load_stage(1); load_stage(2);

    for (int it = 0; it < T; it++) {
        if (it <= T - 3)      cpa_wait<2>();
        else if (it == T - 2) cpa_wait<1>();
        else                  cpa_wait<0>();
        __syncthreads();
        if (it + 3 < T) load_stage(it + 3);

        const float* Asm = As + (it & 3) * 64 * KST;
        const float* Bsm = Bs + (it & 3) * 64 * KST;

        #pragma unroll
        for (int kf = 0; kf < 4; kf++) {
            float af[2][4];
            #pragma unroll
            for (int mt = 0; mt < 2; mt++) {
                const int row = warpM * 32 + mt * 16 + g;
                af[mt][0] = Asm[row * KST + kf * 8 + tig];
                af[mt][1] = Asm[(row + 8) * KST + kf * 8 + tig];
                af[mt][2] = Asm[row * KST + kf * 8 + tig + 4];
                af[mt][3] = Asm[(row + 8) * KST + kf * 8 + tig + 4];
                if (p.cvtA) {
                    af[mt][0] = to_tf32(af[mt][0]); af[mt][1] = to_tf32(af[mt][1]);
                    af[mt][2] = to_tf32(af[mt][2]); af[mt][3] = to_tf32(af[mt][3]);
                }
            }
            #pragma unroll
            for (int nf = 0; nf < 2; nf++) {
                const int brow = warpN * 16 + nf * 8 + g;
                float b0f = Bsm[brow * KST + kf * 8 + tig];
                float b1f = Bsm[brow * KST + kf * 8 + tig + 4];
                if (p.cvtB) { b0f = to_tf32(b0f); b1f = to_tf32(b1f); }
                const uint32_t b0 = __float_as_uint(b0f);
                const uint32_t b1 = __float_as_uint(b1f);
                #pragma unroll
                for (int mt = 0; mt < 2; mt++)
                    MMA1688T(acc[mt][nf],
                             __float_as_uint(af[mt][0]), __float_as_uint(af[mt][1]),
                             __float_as_uint(af[mt][2]), __float_as_uint(af[mt][3]),
                             b0, b1);
            }
        }
        __syncthreads();
    }

    #pragma unroll
    for (int mt = 0; mt < 2; mt++) {
        const int r1 = warpM * 32 + mt * 16 + g;
        const int r2 = r1 + 8;
        #pragma unroll
        for (int nf = 0; nf < 2; nf++) {
            const int ncol = blockIdx.x * 64 + warpN * 16 + nf * 8 + tig * 2;
            *(float2*)(Cp + (size_t)r1 * p.ldc + ncol) =
                make_float2(acc[mt][nf][0], acc[mt][nf][1]);
            *(float2*)(Cp + (size_t)r2 * p.ldc + ncol) =
                make_float2(acc[mt][nf][2], acc[mt][nf][3]);
        }
    }
}

// ---------------------------------------------------------------------------
// fp32 NT GEMM partial (split-K) — decs only.
// ---------------------------------------------------------------------------
__global__ __launch_bounds__(256) void gemm_part_kernel(
    const float* __restrict__ A, int lda,
    const float* __restrict__ W, int ldw,
    float* __restrict__ Cpart, int N, int kchunk)
{
    __shared__ float As[16][64];
    __shared__ float Bs[16][64];
    const int tid = threadIdx.x;
    const int tx = tid & 15, ty = tid >> 4;
    const int n0 = blockIdx.x * 64;
    const int kbase = blockIdx.y * kchunk;
    const int lm = tid >> 2;
    const int lk = (tid & 3) * 4;

    float acc[4][4] = {};
    for (int k0 = 0; k0 < kchunk; k0 += 16) {
        float4 av = *(const float4*)(A + (size_t)lm * lda + kbase + k0 + lk);
        As[lk + 0][lm] = av.x; As[lk + 1][lm] = av.y;
        As[lk + 2][lm] = av.z; As[lk + 3][lm] = av.w;
        float4 bv = *(const float4*)(W + (size_t)(n0 + lm) * ldw + kbase + k0 + lk);
        Bs[lk + 0][lm] = bv.x; Bs[lk + 1][lm] = bv.y;
        Bs[lk + 2][lm] = bv.z; Bs[lk + 3][lm] = bv.w;
        __syncthreads();
        #pragma unroll
        for (int k = 0; k < 16; k++) {
            float4 a = *(const float4*)&As[k][ty * 4];
            float4 b = *(const float4*)&Bs[k][tx * 4];
            acc[0][0] += a.x * b.x; acc[0][1] += a.x * b.y; acc[0][2] += a.x * b.z; acc[0][3] += a.x * b.w;
            acc[1][0] += a.y * b.x; acc[1][1] += a.y * b.y; acc[1][2] += a.y * b.z; acc[1][3] += a.y * b.w;
            acc[2][0] += a.z * b.x; acc[2][1] += a.z * b.y; acc[2][2] += a.z * b.z; acc[2][3] += a.z * b.w;
            acc[3][0] += a.w * b.x; acc[3][1] += a.w * b.y; acc[3][2] += a.w * b.z; acc[3][3] += a.w * b.w;
        }
        __syncthreads();
    }
    float* Cout = Cpart + (size_t)blockIdx.y * 64 * N;
    #pragma unroll
    for (int i = 0; i < 4; i++)
        *(float4*)(Cout + (size_t)(ty * 4 + i) * N + n0 + tx * 4) =
            make_float4(acc[i][0], acc[i][1], acc[i][2], acc[i][3]);
}

// ---------------------------------------------------------------------------
// Fused softmax + context: per (b, h-chunk) block, recompute the 128-wide
// softmax from epart in smem (identical reduction tree to the old softmax
// kernel), then the alpha-weighted sum over enc.  grid=(64,8), block=256.
// ---------------------------------------------------------------------------
__global__ void ctx_alpha_kernel(const float* __restrict__ epart,
                                 const float* __restrict__ enc,
                                 float* __restrict__ ctx)
{
    const int b = blockIdx.x;
    const int h = blockIdx.y * 256 + threadIdx.x;
    __shared__ float sm[128];
    __shared__ float al[128];
    const int l = threadIdx.x;

    float ev = 0.f;
    if (l < 128) {
        const float* p = epart + (size_t)(l * B_ + b) * 4;
        ev = p[0] + p[1] + p[2] + p[3];
        sm[l] = ev;
    }
    __syncthreads();
    for (int o = 64; o > 0; o >>= 1) {
        if (l < o) sm[l] = fmaxf(sm[l], sm[l + o]);
        __syncthreads();
    }
    const float mx = sm[0];
    __syncthreads();
    float ex = 0.f;
    if (l < 128) { ex = expf(ev - mx); sm[l] = ex; }
    __syncthreads();
    for (int o = 64; o > 0; o >>= 1) {
        if (l < o) sm[l] += sm[l + o];
        __syncthreads();
    }
    if (l < 128) al[l] = ex / sm[0];
    __syncthreads();

    float acc = 0.f;
    #pragma unroll 4
    for (int l2 = 0; l2 < LX_; l2++)
        acc += al[l2] * enc[(size_t)(l2 * B_ + b) * H2_ + h];
    ctx[b * H2_ + h] = acc;
}

// -------------------- combiners -------------------------------------------
__global__ void combine_plain(const float* __restrict__ part, int nchunks,
                              int nelem, float* __restrict__ out)
{
    const int i = blockIdx.x * 256 + threadIdx.x;
    if (i >= nelem) return;
    float s = 0.f;
    for (int c = 0; c < nchunks; c++) s += part[(size_t)c * nelem + i];
    out[i] = s;
}

__global__ void combine_rz(const float* __restrict__ part,
                           const float* __restrict__ br, const float* __restrict__ bz,
                           const float* __restrict__ sprev,
                           float* __restrict__ rs, float* __restrict__ z)
{
    const int i = blockIdx.x * 256 + threadIdx.x;
    const int m = i >> 11, n = i & 2047;
    float s = (n < 1024) ? br[n] : bz[n - 1024];
    #pragma unroll
    for (int c = 0; c < 7; c++) s += part[(size_t)c * 64 * 4096 + m * 4096 + n];
    const float v = 1.f / (1.f + expf(-s));
    if (n < 1024) rs[m * 1024 + n] = v * sprev[m * 1024 + n];
    else          z[m * 1024 + n - 1024] = v;
}

__global__ void combine_gru(const float* __restrict__ part, const float* __restrict__ uspart,
                            const float* __restrict__ bs, const float* __restrict__ z,
                            const float* __restrict__ sprev, float* __restrict__ s_out)
{
    const int i = blockIdx.x * 256 + threadIdx.x;
    const int m = i >> 10, n = i & 1023;
    float acc = bs[n];
    const int col = 2048 + n;
    acc += part[(size_t)0 * 64 * 4096 + m * 4096 + col];
    #pragma unroll
    for (int c = 3; c < 7; c++) acc += part[(size_t)c * 64 * 4096 + m * 4096 + col];
    #pragma unroll
    for (int c = 0; c < 4; c++) acc += uspart[c * 65536 + m * 1024 + n];
    const float sp = tanhf(acc);
    const float zz = z[i];
    s_out[i] = zz * sp + (1.f - zz) * sprev[i];
}

__global__ void combine_maxout(const float* __restrict__ part, float* __restrict__ t)
{
    const int i = blockIdx.x * 256 + threadIdx.x;
    const int m = i >> 9, j = i & 511;
    const int c0 = 3072 + 2 * j;
    float v0 = 0.f, v1 = 0.f;
    #pragma unroll
    for (int c = 0; c < 7; c++) {
        const float* p = part + (size_t)c * 64 * 4096 + m * 4096;
        v0 += p[c0]; v1 += p[c0 + 1];
    }
    float r;
    asm("cvt.rna.tf32.f32 %0, %1;" : "=f"(r) : "f"(fmaxf(v0, v1)));
    t[i] = r;
}

// ---------------------------------------------------------------------------
extern "C" void kernel_launch(void* const* d_in, const int* in_sizes, int n_in,
                              void* d_out, int out_size)
{
    const float* x     = (const float*)d_in[0];
    const float* sprev = (const float*)d_in[1];
    const float* enc   = (const float*)d_in[2];
    const float* Ws = (const float*)d_in[4];
    const float* Wz = (const float*)d_in[5];
    const float* Wr = (const float*)d_in[6];
    const float* Us = (const float*)d_in[7];
    const float* Uz = (const float*)d_in[8];
    const float* Ur = (const float*)d_in[9];
    const float* Cs = (const float*)d_in[10];
    const float* Cz = (const float*)d_in[11];
    const float* Cr = (const float*)d_in[12];
    const float* bs = (const float*)d_in[13];
    const float* bz = (const float*)d_in[14];
    const float* br = (const float*)d_in[15];
    const float* va = (const float*)d_in[16];
    const float* Wa = (const float*)d_in[17];
    const float* Ua = (const float*)d_in[18];
    const float* Uo = (const float*)d_in[19];
    const float* Vo = (const float*)d_in[20];
    const float* Co = (const float*)d_in[21];
    const float* Wo = (const float*)d_in[22];

    static float *p_dpart = nullptr, *p_decs, *p_epart, *p_ctx,
                 *p_part, *p_rs, *p_z, *p_t;
    static __nv_bfloat16 *p_encb, *p_uab;
    static cudaStream_t s1, s2;
    static cudaEvent_t ev_root, evA, evB2, evG, ev_root2, evC;
    static int attn_smem = 4 * ATILE * 2 + 128 * 2 * 4;
    static int eng_smem  = 8 * 64 * KST * 4;
    if (!p_dpart) {
        cudaGetSymbolAddress((void**)&p_dpart, g_dpart);
        cudaGetSymbolAddress((void**)&p_decs,  g_decs);
        cudaGetSymbolAddress((void**)&p_epart, g_epart);
        cudaGetSymbolAddress((void**)&p_ctx,   g_ctx);
        cudaGetSymbolAddress((void**)&p_part,  g_part);
        cudaGetSymbolAddress((void**)&p_rs,    g_rs);
        cudaGetSymbolAddress((void**)&p_z,     g_z);
        cudaGetSymbolAddress((void**)&p_t,     g_t);
        cudaGetSymbolAddress((void**)&p_encb,  g_encb);
        cudaGetSymbolAddress((void**)&p_uab,   g_uab);
        cudaFuncSetAttribute(attn_mma_kernel,
                             cudaFuncAttributeMaxDynamicSharedMemorySize, attn_smem);
        cudaFuncSetAttribute(gemm_async_kernel,
                             cudaFuncAttributeMaxDynamicSharedMemorySize, eng_smem);
        cudaStreamCreateWithFlags(&s1, cudaStreamNonBlocking);
        cudaStreamCreateWithFlags(&s2, cudaStreamNonBlocking);
        cudaEventCreateWithFlags(&ev_root, cudaEventDisableTiming);
        cudaEventCreateWithFlags(&evA, cudaEventDisableTiming);
        cudaEventCreateWithFlags(&evB2, cudaEventDisableTiming);
        cudaEventCreateWithFlags(&evG, cudaEventDisableTiming);
        cudaEventCreateWithFlags(&ev_root2, cudaEventDisableTiming);
        cudaEventCreateWithFlags(&evC, cudaEventDisableTiming);
    }

    float* out_s      = (float*)d_out;
    float* out_logits = (float*)d_out + 65536;

    const int HALF = 4096 * 2048;   // half of enc, in elements

    // ---- fork head --------------------------------------------------------
    cudaEventRecord(ev_root, 0);
    cudaStreamWaitEvent(s1, ev_root, 0);
    cudaStreamWaitEvent(s2, ev_root, 0);

    // s2: x/sprev gate chunks (input-only deps) — one fused engine launch
    {
        GemmP p = {};
        const float* Aseq[3] = { x, sprev, sprev + 512 };
        int ldas[3] = { 512, 1024, 1024 };
        for (int c = 0; c < 3; c++) {
            p.A[c] = Aseq[c]; p.lda[c] = ldas[c]; p.ldw[c] = ldas[c];
            p.C[c] = p_part + (size_t)c * 64 * 4096;
        }
        const float* Wt[4][3] = {
            { Wr, Ur, Ur + 512 },
            { Wz, Uz, Uz + 512 },
            { Ws, nullptr, nullptr },
            { Vo, Uo, Uo + 512 },
        };
        for (int gg = 0; gg < 4; gg++)
            for (int c = 0; c < 3; c++) p.W[gg][c] = Wt[gg][c];
        p.ldc = 4096; p.gshift = 4; p.gate_cols = 1024;
        p.kiters = 16; p.cvtA = 1; p.cvtB = 1;
        gemm_async_kernel<<<dim3(64, 3), 256, eng_smem, s2>>>(p);
    }
    cudaEventRecord(evG, s2);

    // s1: Ua conversion, decs chain, enc upper-half conversion, attn upper half
    f2bf_kernel<<<1024, 256, 0, s1>>>(Ua, p_uab, 512 * 2048);
    gemm_part_kernel<<<dim3(8, 8), 256, 0, s1>>>(sprev, HID_, Wa, HID_, p_dpart, ATN_, 128);
    combine_plain<<<128, 256, 0, s1>>>(p_dpart, 8, 64 * ATN_, p_decs);
    cudaEventRecord(evA, s1);
    f2bf_kernel<<<8192, 256, 0, s1>>>(enc + HALF, p_encb + HALF, HALF);
    attn_mma_kernel<<<dim3(32, 4), 256, attn_smem, s1>>>(
        p_encb, p_uab, p_decs, va, p_epart, 4096);
    cudaEventRecord(evB2, s1);

    // main: enc lower-half conversion, attention lower half
    f2bf_kernel<<<8192, 256>>>(enc, p_encb, HALF);
    cudaStreamWaitEvent(0, evA, 0);
    attn_mma_kernel<<<dim3(32, 4), 256, attn_smem>>>(
        p_encb, p_uab, p_decs, va, p_epart, 0);

    // join both attention halves, then fused softmax+ctx, then ctx-gates
    cudaStreamWaitEvent(0, evB2, 0);
    ctx_alpha_kernel<<<dim3(64, 8), 256>>>(p_epart, enc, p_ctx);
    {
        GemmP p = {};
        for (int c = 0; c < 4; c++) {
            p.A[c] = p_ctx + c * 512;
            p.lda[c] = 2048; p.ldw[c] = 2048;
            p.C[c] = p_part + (size_t)(c + 3) * 64 * 4096;
        }
        const float* Wt[4][4] = {
            { Cr, Cr + 512, Cr + 1024, Cr + 1536 },
            { Cz, Cz + 512, Cz + 1024, Cz + 1536 },
            { Cs, Cs + 512, Cs + 1024, Cs + 1536 },
            { Co, Co + 512, Co + 1024, Co + 1536 },
        };
        for (int gg = 0; gg < 4; gg++)
            for (int c = 0; c < 4; c++) p.W[gg][c] = Wt[gg][c];
        p.ldc = 4096; p.gshift = 4; p.gate_cols = 1024;
        p.kiters = 16; p.cvtA = 1; p.cvtB = 1;
        gemm_async_kernel<<<dim3(64, 4), 256, eng_smem>>>(p);
    }

    // join x/sprev gates, nonlinearities
    cudaStreamWaitEvent(0, evG, 0);
    combine_rz<<<512, 256>>>(p_part, br, bz, sprev, p_rs, p_z);

    // ---- fork tail --------------------------------------------------------
    cudaEventRecord(ev_root2, 0);
    cudaStreamWaitEvent(s1, ev_root2, 0);

    // s1: rs @ Us^T then GRU blend -> out_s
    {
        GemmP p = {};
        for (int c = 0; c < 4; c++) {
            p.A[c] = p_rs + c * 256;
            p.lda[c] = 1024; p.ldw[c] = 1024;
            p.W[0][c] = Us + c * 256;
            p.C[c] = p_dpart + (size_t)c * 65536;
        }
        p.ldc = 1024; p.gshift = 16; p.gate_cols = 0;
        p.kiters = 8; p.cvtA = 1; p.cvtB = 1;
        gemm_async_kernel<<<dim3(16, 4), 256, eng_smem, s1>>>(p);
    }
    combine_gru<<<256, 256, 0, s1>>>(p_part, p_dpart, bs, p_z, sprev, out_s);
    cudaEventRecord(evC, s1);

    // main: maxout -> t -> logits (Wo read directly, cvt in fragment path)
    combine_maxout<<<128, 256>>>(p_part, p_t);
    {
        GemmP p = {};
        p.A[0] = p_t; p.lda[0] = 512;
        p.W[0][0] = Wo; p.ldw[0] = 512;
        p.C[0] = out_logits; p.ldc = VOC_;
        p.gshift = 16; p.gate_cols = 0;
        p.kiters = 16; p.cvtA = 0; p.cvtB = 1;
        gemm_async_kernel<<<dim3(500, 1), 256, eng_smem>>>(p);
    }
    cudaStreamWaitEvent(0, evC, 0);
}